// round 1
// baseline (speedup 1.0000x reference)
#include <cuda_runtime.h>
#include <cstdint>

typedef unsigned long long ull;

// ---------- packed f32x2 helpers (each half is an exact IEEE fp32 op) ----------
__device__ __forceinline__ ull pack2(float lo, float hi){
    ull r; asm("mov.b64 %0, {%1,%2};" : "=l"(r) : "f"(lo), "f"(hi)); return r;
}
__device__ __forceinline__ void unpack2(ull v, float& lo, float& hi){
    asm("mov.b64 {%0,%1}, %2;" : "=f"(lo), "=f"(hi) : "l"(v));
}
__device__ __forceinline__ ull fma2(ull a, ull b, ull c){
    ull d; asm("fma.rn.f32x2 %0, %1, %2, %3;" : "=l"(d) : "l"(a), "l"(b), "l"(c)); return d;
}
__device__ __forceinline__ ull add2(ull a, ull b){
    ull d; asm("add.rn.f32x2 %0, %1, %2;" : "=l"(d) : "l"(a), "l"(b)); return d;
}
__device__ __forceinline__ ull mul2(ull a, ull b){
    ull d; asm("mul.rn.f32x2 %0, %1, %2;" : "=l"(d) : "l"(a), "l"(b)); return d;
}

// ---------- problem constants ----------
constexpr int KCODES = 512;
constexpr int SUBD   = 32;
constexpr int NCB    = 8;
constexpr int TPB    = 512;   // threads per block; each thread handles 2 tokens

// ---------- scratch (no allocation allowed) ----------
__device__ double g_sqsum;
__device__ float  g_hist[NCB * KCODES];

__global__ void vq_zero(){
    int i = blockIdx.x * blockDim.x + threadIdx.x;
    if (i < NCB * KCODES) g_hist[i] = 0.f;
    if (i == 0) g_sqsum = 0.0;
}

// shared memory layout
constexpr int SM_CB   = KCODES * SUBD * (int)sizeof(float2);  // 131072 duplicated codebook
constexpr int SM_C2   = KCODES * (int)sizeof(float2);         // 4096   duplicated ||e||^2
constexpr int SM_HIST = KCODES * (int)sizeof(float);          // 2048
constexpr int SM_RED  = TPB * (int)sizeof(double);            // 4096
constexpr int SM_TOTAL = SM_CB + SM_C2 + SM_HIST + SM_RED;

__global__ __launch_bounds__(TPB, 1)
void vq_main(const float* __restrict__ latents,
             const float* __restrict__ mask,
             const float* __restrict__ codebooks,
             float* __restrict__ out_ids,
             float* __restrict__ out_q,
             float* __restrict__ out_st)
{
    extern __shared__ char smem[];
    float2* s_cb   = (float2*)(smem);
    float2* s_c2   = (float2*)(smem + SM_CB);
    float*  s_hist = (float*) (smem + SM_CB + SM_C2);
    double* s_red  = (double*)(smem + SM_CB + SM_C2 + SM_HIST);

    const int c   = blockIdx.y;
    const int tid = threadIdx.x;

    // load codebook c as duplicated pairs {v,v}
    const float* cbc = codebooks + (size_t)c * KCODES * SUBD;
    for (int i = tid; i < KCODES * SUBD; i += TPB){
        float v = cbc[i];
        s_cb[i] = make_float2(v, v);
    }
    s_hist[tid] = 0.f;
    __syncthreads();

    // c2[k] = sum_d round(e*e), sequential adds (replicates (codebooks**2).sum(-1))
    {
        float acc = 0.f;
        const float2* row = s_cb + tid * SUBD;
        #pragma unroll
        for (int d = 0; d < SUBD; d++){
            float e = row[d].x;
            acc = __fadd_rn(acc, __fmul_rn(e, e));
        }
        s_c2[tid] = make_float2(acc, acc);
    }
    __syncthreads();

    const int t0 = blockIdx.x * (2 * TPB) + tid;
    const int t1 = t0 + TPB;

    // load this thread's two sub-vectors, packed {x_t0, x_t1}
    ull xp[SUBD];
    {
        const float4* p0 = (const float4*)(latents + (size_t)t0 * 256 + c * SUBD);
        const float4* p1 = (const float4*)(latents + (size_t)t1 * 256 + c * SUBD);
        #pragma unroll
        for (int i = 0; i < 8; i++){
            float4 a = p0[i], b = p1[i];
            xp[4*i+0] = pack2(a.x, b.x);
            xp[4*i+1] = pack2(a.y, b.y);
            xp[4*i+2] = pack2(a.z, b.z);
            xp[4*i+3] = pack2(a.w, b.w);
        }
    }

    // x2 = sum_d round(x*x), sequential (replicates (x**2).sum(-1))
    ull x2 = pack2(0.f, 0.f);
    #pragma unroll
    for (int d = 0; d < SUBD; d++) x2 = add2(x2, mul2(xp[d], xp[d]));

    const ull NEG2 = pack2(-2.f, -2.f);
    float best0 = 3.4e38f, best1 = 3.4e38f;
    int id0 = 0, id1 = 0;

    #pragma unroll 2
    for (int k = 0; k < KCODES; k++){
        const ulonglong2* ek = (const ulonglong2*)(s_cb + k * SUBD);
        ull dot = pack2(0.f, 0.f);
        #pragma unroll
        for (int d = 0; d < SUBD / 2; d++){
            ulonglong2 e2 = ek[d];
            dot = fma2(xp[2*d],   e2.x, dot);   // sequential fp32 fma chain (d ascending)
            dot = fma2(xp[2*d+1], e2.y, dot);
        }
        // term1 = round(x2 + c2[k]); dist = round(term1 - 2*dot)  (2*dot exact)
        ull term = add2(x2, *(const ull*)(s_c2 + k));
        ull dist = fma2(dot, NEG2, term);
        float d0, d1; unpack2(dist, d0, d1);
        if (d0 < best0){ best0 = d0; id0 = k; }   // strict <, keep first index
        if (d1 < best1){ best1 = d1; id1 = k; }
    }

    // epilogue: quant, st_quantized, loss accumulation
    float lsum = 0.f;
    {
        const float2* q0 = s_cb + id0 * SUBD;
        const float2* q1 = s_cb + id1 * SUBD;
        float4* oq0 = (float4*)(out_q  + (size_t)t0 * 256 + c * SUBD);
        float4* oq1 = (float4*)(out_q  + (size_t)t1 * 256 + c * SUBD);
        float4* os0 = (float4*)(out_st + (size_t)t0 * 256 + c * SUBD);
        float4* os1 = (float4*)(out_st + (size_t)t1 * 256 + c * SUBD);
        #pragma unroll
        for (int i = 0; i < 8; i++){
            float4 qv0, qv1, sv0, sv1;
            float* pq0 = (float*)&qv0; float* pq1 = (float*)&qv1;
            float* ps0 = (float*)&sv0; float* ps1 = (float*)&sv1;
            #pragma unroll
            for (int j = 0; j < 4; j++){
                int d = 4*i + j;
                float xv0, xv1; unpack2(xp[d], xv0, xv1);
                float q0v = q0[d].x, q1v = q1[d].x;
                pq0[j] = q0v; pq1[j] = q1v;
                // st = l + (q - l), each op fp32-rounded (matches jax)
                ps0[j] = __fadd_rn(xv0, __fsub_rn(q0v, xv0));
                ps1[j] = __fadd_rn(xv1, __fsub_rn(q1v, xv1));
                float e0 = xv0 - q0v, e1 = xv1 - q1v;
                lsum = fmaf(e0, e0, lsum);
                lsum = fmaf(e1, e1, lsum);
            }
            oq0[i] = qv0; oq1[i] = qv1;
            os0[i] = sv0; os1[i] = sv1;
        }
    }
    out_ids[(size_t)t0 * NCB + c] = (float)id0;
    out_ids[(size_t)t1 * NCB + c] = (float)id1;

    atomicAdd(&s_hist[id0], mask[t0]);
    atomicAdd(&s_hist[id1], mask[t1]);

    s_red[tid] = (double)lsum;
    __syncthreads();
    for (int s = TPB / 2; s > 0; s >>= 1){
        if (tid < s) s_red[tid] += s_red[tid + s];
        __syncthreads();
    }
    if (tid == 0) atomicAdd(&g_sqsum, s_red[0]);
    atomicAdd(&g_hist[c * KCODES + tid], s_hist[tid]);
}

__global__ void vq_finalize(const float* __restrict__ mask,
                            float* __restrict__ out_scalars,
                            int ntok)
{
    __shared__ double dred[512];
    __shared__ float  fred[512];
    __shared__ float  pp[NCB];
    int tid = threadIdx.x;

    double s = 0.0;
    for (int i = tid; i < ntok; i += 512) s += (double)mask[i];
    dred[tid] = s; __syncthreads();
    for (int st = 256; st > 0; st >>= 1){
        if (tid < st) dred[tid] += dred[tid + st];
        __syncthreads();
    }
    float denom = fmaxf((float)dred[0], 1.0f);

    for (int c = 0; c < NCB; c++){
        float p = __fdiv_rn(g_hist[c * KCODES + tid], denom);
        float t = __fmul_rn(p, logf(__fadd_rn(p, 1e-8f)));
        fred[tid] = t; __syncthreads();
        for (int st = 256; st > 0; st >>= 1){
            if (tid < st) fred[tid] += fred[tid + st];
            __syncthreads();
        }
        if (tid == 0) pp[c] = expf(-fred[0]);
        __syncthreads();
    }
    if (tid == 0){
        float ppl = (((((((pp[0] + pp[1]) + pp[2]) + pp[3]) + pp[4]) + pp[5]) + pp[6]) + pp[7]) / 8.f;
        double cnt = (double)ntok * 256.0;
        double mse = g_sqsum / cnt;
        out_scalars[0] = (float)(mse * 0.25);  // commitment_loss
        out_scalars[1] = (float)mse;           // codebook_loss
        out_scalars[2] = ppl;                  // perplexity
    }
}

extern "C" void kernel_launch(void* const* d_in, const int* in_sizes, int n_in,
                              void* d_out, int out_size)
{
    const float* latents   = (const float*)d_in[0];
    const float* mask      = (const float*)d_in[1];
    const float* codebooks = (const float*)d_in[2];
    float* out = (float*)d_out;

    const int ntok = in_sizes[1];           // B*N = 65536
    const size_t ids_n = (size_t)ntok * NCB;
    const size_t qn    = (size_t)ntok * 256;

    float* out_ids = out;
    float* out_q   = out + ids_n;
    float* out_st  = out_q + qn;
    float* out_sc  = out_st + qn;

    cudaFuncSetAttribute(vq_main, cudaFuncAttributeMaxDynamicSharedMemorySize, SM_TOTAL);

    vq_zero<<<8, 512>>>();
    dim3 grid(ntok / (2 * TPB), NCB);
    vq_main<<<grid, TPB, SM_TOTAL>>>(latents, mask, codebooks, out_ids, out_q, out_st);
    vq_finalize<<<1, 512>>>(mask, out_sc, ntok);
}

// round 2
// speedup vs baseline: 1.1731x; 1.1731x over previous
#include <cuda_runtime.h>
#include <cstdint>

typedef unsigned long long ull;

// ---------- packed f32x2 helpers (each half is an exact IEEE fp32 op) ----------
__device__ __forceinline__ ull pack2(float lo, float hi){
    ull r; asm("mov.b64 %0, {%1,%2};" : "=l"(r) : "f"(lo), "f"(hi)); return r;
}
__device__ __forceinline__ void unpack2(ull v, float& lo, float& hi){
    asm("mov.b64 {%0,%1}, %2;" : "=f"(lo), "=f"(hi) : "l"(v));
}
__device__ __forceinline__ ull fma2(ull a, ull b, ull c){
    ull d; asm("fma.rn.f32x2 %0, %1, %2, %3;" : "=l"(d) : "l"(a), "l"(b), "l"(c)); return d;
}
__device__ __forceinline__ ull add2(ull a, ull b){
    ull d; asm("add.rn.f32x2 %0, %1, %2;" : "=l"(d) : "l"(a), "l"(b)); return d;
}
__device__ __forceinline__ ull mul2(ull a, ull b){
    ull d; asm("mul.rn.f32x2 %0, %1, %2;" : "=l"(d) : "l"(a), "l"(b)); return d;
}

// ---------- problem constants ----------
constexpr int KCODES = 512;
constexpr int SUBD   = 32;
constexpr int NCB    = 8;
constexpr int TPB    = 256;     // 4 tokens per thread -> 1024 tokens per block

// ---------- scratch (no allocation allowed) ----------
__device__ double g_sqsum;
__device__ float  g_hist[NCB * KCODES];

__global__ void vq_zero(){
    int i = blockIdx.x * blockDim.x + threadIdx.x;
    if (i < NCB * KCODES) g_hist[i] = 0.f;
    if (i == 0) g_sqsum = 0.0;
}

// shared memory layout
constexpr int SM_CB   = KCODES * SUBD * (int)sizeof(float2);  // 131072 duplicated codebook
constexpr int SM_C2   = KCODES * (int)sizeof(float2);         // 4096   duplicated ||e||^2
constexpr int SM_HIST = KCODES * (int)sizeof(float);          // 2048
constexpr int SM_RED  = TPB * (int)sizeof(double);            // 2048
constexpr int SM_TOTAL = SM_CB + SM_C2 + SM_HIST + SM_RED;

__global__ __launch_bounds__(TPB, 1)
void vq_main(const float* __restrict__ latents,
             const float* __restrict__ mask,
             const float* __restrict__ codebooks,
             float* __restrict__ out_ids,
             float* __restrict__ out_q,
             float* __restrict__ out_st)
{
    extern __shared__ char smem[];
    float2* s_cb   = (float2*)(smem);
    float2* s_c2   = (float2*)(smem + SM_CB);
    float*  s_hist = (float*) (smem + SM_CB + SM_C2);
    double* s_red  = (double*)(smem + SM_CB + SM_C2 + SM_HIST);

    const int c   = blockIdx.y;
    const int tid = threadIdx.x;

    // load codebook c as duplicated pairs {v,v}
    const float* cbc = codebooks + (size_t)c * KCODES * SUBD;
    for (int i = tid; i < KCODES * SUBD; i += TPB){
        float v = cbc[i];
        s_cb[i] = make_float2(v, v);
    }
    s_hist[tid] = 0.f;
    s_hist[tid + TPB] = 0.f;
    __syncthreads();

    // c2[k] = sum_d round(e*e), sequential adds (replicates (codebooks**2).sum(-1))
    #pragma unroll
    for (int k = tid; k < KCODES; k += TPB){
        float acc = 0.f;
        const float2* row = s_cb + k * SUBD;
        #pragma unroll
        for (int d = 0; d < SUBD; d++){
            float e = row[d].x;
            acc = __fadd_rn(acc, __fmul_rn(e, e));
        }
        s_c2[k] = make_float2(acc, acc);
    }
    __syncthreads();

    // 4 tokens per thread: pair A = (t0, t1), pair B = (t2, t3)
    const int t0 = blockIdx.x * (4 * TPB) + tid;
    const int t1 = t0 + TPB;
    const int t2 = t0 + 2 * TPB;
    const int t3 = t0 + 3 * TPB;

    ull xA[SUBD], xB[SUBD];
    {
        const float4* p0 = (const float4*)(latents + (size_t)t0 * 256 + c * SUBD);
        const float4* p1 = (const float4*)(latents + (size_t)t1 * 256 + c * SUBD);
        const float4* p2 = (const float4*)(latents + (size_t)t2 * 256 + c * SUBD);
        const float4* p3 = (const float4*)(latents + (size_t)t3 * 256 + c * SUBD);
        #pragma unroll
        for (int i = 0; i < 8; i++){
            float4 a = p0[i], b = p1[i];
            xA[4*i+0] = pack2(a.x, b.x);
            xA[4*i+1] = pack2(a.y, b.y);
            xA[4*i+2] = pack2(a.z, b.z);
            xA[4*i+3] = pack2(a.w, b.w);
        }
        #pragma unroll
        for (int i = 0; i < 8; i++){
            float4 a = p2[i], b = p3[i];
            xB[4*i+0] = pack2(a.x, b.x);
            xB[4*i+1] = pack2(a.y, b.y);
            xB[4*i+2] = pack2(a.z, b.z);
            xB[4*i+3] = pack2(a.w, b.w);
        }
    }

    // x2 = sum_d round(x*x), sequential (replicates (x**2).sum(-1))
    ull x2A = pack2(0.f, 0.f), x2B = pack2(0.f, 0.f);
    #pragma unroll
    for (int d = 0; d < SUBD; d++) x2A = add2(x2A, mul2(xA[d], xA[d]));
    #pragma unroll
    for (int d = 0; d < SUBD; d++) x2B = add2(x2B, mul2(xB[d], xB[d]));

    const ull NEG2 = pack2(-2.f, -2.f);
    float ba0 = 3.4e38f, ba1 = 3.4e38f, bb0 = 3.4e38f, bb1 = 3.4e38f;
    int ia0 = 0, ia1 = 0, ib0 = 0, ib1 = 0;

    for (int k = 0; k < KCODES; k++){
        const ulonglong2* ek = (const ulonglong2*)(s_cb + k * SUBD);
        ull dotA = pack2(0.f, 0.f), dotB = pack2(0.f, 0.f);
        #pragma unroll
        for (int d = 0; d < SUBD / 2; d++){
            ulonglong2 e2 = ek[d];                 // one LDS.128 feeds 4 fma2
            dotA = fma2(xA[2*d],   e2.x, dotA);    // sequential fp32 fma chain (d ascending)
            dotB = fma2(xB[2*d],   e2.x, dotB);
            dotA = fma2(xA[2*d+1], e2.y, dotA);
            dotB = fma2(xB[2*d+1], e2.y, dotB);
        }
        ull c2k = *(const ull*)(s_c2 + k);
        // term = round(x2 + c2[k]); dist = round(term - 2*dot)  (2*dot exact)
        ull distA = fma2(dotA, NEG2, add2(x2A, c2k));
        ull distB = fma2(dotB, NEG2, add2(x2B, c2k));
        float dA0, dA1, dB0, dB1;
        unpack2(distA, dA0, dA1);
        unpack2(distB, dB0, dB1);
        if (dA0 < ba0){ ba0 = dA0; ia0 = k; }   // strict <, keep first index
        if (dA1 < ba1){ ba1 = dA1; ia1 = k; }
        if (dB0 < bb0){ bb0 = dB0; ib0 = k; }
        if (dB1 < bb1){ bb1 = dB1; ib1 = k; }
    }

    // epilogue: quant, st_quantized, loss accumulation
    float lsum = 0.f;
    {
        const int ids4[4]  = {ia0, ia1, ib0, ib1};
        const int toks[4]  = {t0, t1, t2, t3};
        #pragma unroll
        for (int s = 0; s < 4; s++){
            const float2* q = s_cb + ids4[s] * SUBD;
            float4* oq = (float4*)(out_q  + (size_t)toks[s] * 256 + c * SUBD);
            float4* os = (float4*)(out_st + (size_t)toks[s] * 256 + c * SUBD);
            const ull* xp = (s < 2) ? xA : xB;
            const int lane = s & 1;
            #pragma unroll
            for (int i = 0; i < 8; i++){
                float4 qv, sv;
                float* pq = (float*)&qv; float* ps = (float*)&sv;
                #pragma unroll
                for (int j = 0; j < 4; j++){
                    int d = 4*i + j;
                    float xlo, xhi; unpack2(xp[d], xlo, xhi);
                    float xv = lane ? xhi : xlo;
                    float qv1 = q[d].x;
                    pq[j] = qv1;
                    // st = l + (q - l), each op fp32-rounded (matches jax)
                    ps[j] = __fadd_rn(xv, __fsub_rn(qv1, xv));
                    float e = xv - qv1;
                    lsum = fmaf(e, e, lsum);
                }
                oq[i] = qv;
                os[i] = sv;
            }
            out_ids[(size_t)toks[s] * NCB + c] = (float)ids4[s];
        }
    }

    atomicAdd(&s_hist[ia0], mask[t0]);
    atomicAdd(&s_hist[ia1], mask[t1]);
    atomicAdd(&s_hist[ib0], mask[t2]);
    atomicAdd(&s_hist[ib1], mask[t3]);

    s_red[tid] = (double)lsum;
    __syncthreads();
    for (int s = TPB / 2; s > 0; s >>= 1){
        if (tid < s) s_red[tid] += s_red[tid + s];
        __syncthreads();
    }
    if (tid == 0) atomicAdd(&g_sqsum, s_red[0]);
    atomicAdd(&g_hist[c * KCODES + tid], s_hist[tid]);
    atomicAdd(&g_hist[c * KCODES + tid + TPB], s_hist[tid + TPB]);
}

__global__ void vq_finalize(const float* __restrict__ mask,
                            float* __restrict__ out_scalars,
                            int ntok)
{
    __shared__ double dred[512];
    __shared__ float  fred[512];
    __shared__ float  pp[NCB];
    int tid = threadIdx.x;

    double s = 0.0;
    for (int i = tid; i < ntok; i += 512) s += (double)mask[i];
    dred[tid] = s; __syncthreads();
    for (int st = 256; st > 0; st >>= 1){
        if (tid < st) dred[tid] += dred[tid + st];
        __syncthreads();
    }
    float denom = fmaxf((float)dred[0], 1.0f);

    for (int c = 0; c < NCB; c++){
        float p = __fdiv_rn(g_hist[c * KCODES + tid], denom);
        float t = __fmul_rn(p, logf(__fadd_rn(p, 1e-8f)));
        fred[tid] = t; __syncthreads();
        for (int st = 256; st > 0; st >>= 1){
            if (tid < st) fred[tid] += fred[tid + st];
            __syncthreads();
        }
        if (tid == 0) pp[c] = expf(-fred[0]);
        __syncthreads();
    }
    if (tid == 0){
        float ppl = (((((((pp[0] + pp[1]) + pp[2]) + pp[3]) + pp[4]) + pp[5]) + pp[6]) + pp[7]) / 8.f;
        double cnt = (double)ntok * 256.0;
        double mse = g_sqsum / cnt;
        out_scalars[0] = (float)(mse * 0.25);  // commitment_loss
        out_scalars[1] = (float)mse;           // codebook_loss
        out_scalars[2] = ppl;                  // perplexity
    }
}

extern "C" void kernel_launch(void* const* d_in, const int* in_sizes, int n_in,
                              void* d_out, int out_size)
{
    const float* latents   = (const float*)d_in[0];
    const float* mask      = (const float*)d_in[1];
    const float* codebooks = (const float*)d_in[2];
    float* out = (float*)d_out;

    const int ntok = in_sizes[1];           // B*N = 65536
    const size_t ids_n = (size_t)ntok * NCB;
    const size_t qn    = (size_t)ntok * 256;

    float* out_ids = out;
    float* out_q   = out + ids_n;
    float* out_st  = out_q + qn;
    float* out_sc  = out_st + qn;

    cudaFuncSetAttribute(vq_main, cudaFuncAttributeMaxDynamicSharedMemorySize, SM_TOTAL);

    vq_zero<<<8, 512>>>();
    dim3 grid(ntok / (4 * TPB), NCB);
    vq_main<<<grid, TPB, SM_TOTAL>>>(latents, mask, codebooks, out_ids, out_q, out_st);
    vq_finalize<<<1, 512>>>(mask, out_sc, ntok);
}

// round 3
// speedup vs baseline: 1.1736x; 1.0004x over previous
#include <cuda_runtime.h>
#include <cstdint>

typedef unsigned long long ull;

// ---------- packed f32x2 helpers (each half is an exact IEEE fp32 op) ----------
__device__ __forceinline__ ull pack2(float lo, float hi){
    ull r; asm("mov.b64 %0, {%1,%2};" : "=l"(r) : "f"(lo), "f"(hi)); return r;
}
__device__ __forceinline__ void unpack2(ull v, float& lo, float& hi){
    asm("mov.b64 {%0,%1}, %2;" : "=f"(lo), "=f"(hi) : "l"(v));
}
__device__ __forceinline__ ull fma2(ull a, ull b, ull c){
    ull d; asm("fma.rn.f32x2 %0, %1, %2, %3;" : "=l"(d) : "l"(a), "l"(b), "l"(c)); return d;
}
__device__ __forceinline__ ull add2(ull a, ull b){
    ull d; asm("add.rn.f32x2 %0, %1, %2;" : "=l"(d) : "l"(a), "l"(b)); return d;
}
__device__ __forceinline__ ull mul2(ull a, ull b){
    ull d; asm("mul.rn.f32x2 %0, %1, %2;" : "=l"(d) : "l"(a), "l"(b)); return d;
}

// ---------- problem constants ----------
constexpr int KCODES = 512;
constexpr int SUBD   = 32;
constexpr int NCB    = 8;
constexpr int TPB    = 256;     // 4 tokens per thread -> 1024 tokens per block

// ---------- scratch (no allocation allowed) ----------
__device__ double g_sqsum;
__device__ float  g_hist[NCB * KCODES];

__global__ void vq_zero(){
    int i = blockIdx.x * blockDim.x + threadIdx.x;
    if (i < NCB * KCODES) g_hist[i] = 0.f;
    if (i == 0) g_sqsum = 0.0;
}

// tiny pad kernels: shift launch indices so ncu (-s 5 -c 1) lands on vq_main
__global__ void vq_pad(){}

// shared memory layout
constexpr int SM_CB   = KCODES * SUBD * (int)sizeof(float2);  // 131072 duplicated codebook
constexpr int SM_C2   = KCODES * (int)sizeof(float2);         // 4096   duplicated ||e||^2
constexpr int SM_HIST = KCODES * (int)sizeof(float);          // 2048
constexpr int SM_RED  = TPB * (int)sizeof(double);            // 2048
constexpr int SM_TOTAL = SM_CB + SM_C2 + SM_HIST + SM_RED;

__global__ __launch_bounds__(TPB, 1)
void vq_main(const float* __restrict__ latents,
             const float* __restrict__ mask,
             const float* __restrict__ codebooks,
             float* __restrict__ out_ids,
             float* __restrict__ out_q,
             float* __restrict__ out_st)
{
    extern __shared__ char smem[];
    float2* s_cb   = (float2*)(smem);
    float2* s_c2   = (float2*)(smem + SM_CB);
    float*  s_hist = (float*) (smem + SM_CB + SM_C2);
    double* s_red  = (double*)(smem + SM_CB + SM_C2 + SM_HIST);

    const int c   = blockIdx.y;
    const int tid = threadIdx.x;

    // load codebook c as duplicated pairs {v,v}
    const float* cbc = codebooks + (size_t)c * KCODES * SUBD;
    for (int i = tid; i < KCODES * SUBD; i += TPB){
        float v = cbc[i];
        s_cb[i] = make_float2(v, v);
    }
    s_hist[tid] = 0.f;
    s_hist[tid + TPB] = 0.f;
    __syncthreads();

    // c2[k] = sum_d round(e*e), sequential adds (replicates (codebooks**2).sum(-1))
    #pragma unroll
    for (int k = tid; k < KCODES; k += TPB){
        float acc = 0.f;
        const float2* row = s_cb + k * SUBD;
        #pragma unroll
        for (int d = 0; d < SUBD; d++){
            float e = row[d].x;
            acc = __fadd_rn(acc, __fmul_rn(e, e));
        }
        s_c2[k] = make_float2(acc, acc);
    }
    __syncthreads();

    // 4 tokens per thread: pair A = (t0, t1), pair B = (t2, t3)
    const int t0 = blockIdx.x * (4 * TPB) + tid;
    const int t1 = t0 + TPB;
    const int t2 = t0 + 2 * TPB;
    const int t3 = t0 + 3 * TPB;

    ull xA[SUBD], xB[SUBD];
    {
        const float4* p0 = (const float4*)(latents + (size_t)t0 * 256 + c * SUBD);
        const float4* p1 = (const float4*)(latents + (size_t)t1 * 256 + c * SUBD);
        const float4* p2 = (const float4*)(latents + (size_t)t2 * 256 + c * SUBD);
        const float4* p3 = (const float4*)(latents + (size_t)t3 * 256 + c * SUBD);
        #pragma unroll
        for (int i = 0; i < 8; i++){
            float4 a = p0[i], b = p1[i];
            xA[4*i+0] = pack2(a.x, b.x);
            xA[4*i+1] = pack2(a.y, b.y);
            xA[4*i+2] = pack2(a.z, b.z);
            xA[4*i+3] = pack2(a.w, b.w);
        }
        #pragma unroll
        for (int i = 0; i < 8; i++){
            float4 a = p2[i], b = p3[i];
            xB[4*i+0] = pack2(a.x, b.x);
            xB[4*i+1] = pack2(a.y, b.y);
            xB[4*i+2] = pack2(a.z, b.z);
            xB[4*i+3] = pack2(a.w, b.w);
        }
    }

    // x2 = sum_d round(x*x), sequential (replicates (x**2).sum(-1))
    ull x2A = pack2(0.f, 0.f), x2B = pack2(0.f, 0.f);
    #pragma unroll
    for (int d = 0; d < SUBD; d++) x2A = add2(x2A, mul2(xA[d], xA[d]));
    #pragma unroll
    for (int d = 0; d < SUBD; d++) x2B = add2(x2B, mul2(xB[d], xB[d]));

    const ull NEG2 = pack2(-2.f, -2.f);
    float ba0 = 3.4e38f, ba1 = 3.4e38f, bb0 = 3.4e38f, bb1 = 3.4e38f;
    int ia0 = 0, ia1 = 0, ib0 = 0, ib1 = 0;

    // Two codes per iteration -> 4 independent fma2 chains.
    // Each chain still accumulates d = 0..31 sequentially (bit-identical dist).
    for (int k = 0; k < KCODES; k += 2){
        const ulonglong2* ek0 = (const ulonglong2*)(s_cb + k * SUBD);
        const ulonglong2* ek1 = (const ulonglong2*)(s_cb + (k + 1) * SUBD);
        ull dA0 = pack2(0.f, 0.f), dB0 = pack2(0.f, 0.f);
        ull dA1 = pack2(0.f, 0.f), dB1 = pack2(0.f, 0.f);
        #pragma unroll
        for (int d = 0; d < SUBD / 2; d++){
            ulonglong2 e0 = ek0[d];            // LDS.128 (broadcast)
            ulonglong2 e1 = ek1[d];
            ull xa = xA[2*d], xa2 = xA[2*d+1];
            ull xb = xB[2*d], xb2 = xB[2*d+1];
            dA0 = fma2(xa,  e0.x, dA0);
            dB0 = fma2(xb,  e0.x, dB0);
            dA1 = fma2(xa,  e1.x, dA1);
            dB1 = fma2(xb,  e1.x, dB1);
            dA0 = fma2(xa2, e0.y, dA0);
            dB0 = fma2(xb2, e0.y, dB0);
            dA1 = fma2(xa2, e1.y, dA1);
            dB1 = fma2(xb2, e1.y, dB1);
        }
        ull c2k0 = *(const ull*)(s_c2 + k);
        ull c2k1 = *(const ull*)(s_c2 + k + 1);
        // term = round(x2 + c2[k]); dist = round(term - 2*dot)  (2*dot exact)
        ull distA0 = fma2(dA0, NEG2, add2(x2A, c2k0));
        ull distB0 = fma2(dB0, NEG2, add2(x2B, c2k0));
        ull distA1 = fma2(dA1, NEG2, add2(x2A, c2k1));
        ull distB1 = fma2(dB1, NEG2, add2(x2B, c2k1));
        float a0l, a0h, b0l, b0h, a1l, a1h, b1l, b1h;
        unpack2(distA0, a0l, a0h);
        unpack2(distB0, b0l, b0h);
        unpack2(distA1, a1l, a1h);
        unpack2(distB1, b1l, b1h);
        // strict <, ascending k order preserved (k before k+1)
        if (a0l < ba0){ ba0 = a0l; ia0 = k; }
        if (a0h < ba1){ ba1 = a0h; ia1 = k; }
        if (b0l < bb0){ bb0 = b0l; ib0 = k; }
        if (b0h < bb1){ bb1 = b0h; ib1 = k; }
        if (a1l < ba0){ ba0 = a1l; ia0 = k + 1; }
        if (a1h < ba1){ ba1 = a1h; ia1 = k + 1; }
        if (b1l < bb0){ bb0 = b1l; ib0 = k + 1; }
        if (b1h < bb1){ bb1 = b1h; ib1 = k + 1; }
    }

    // epilogue: quant, st_quantized, loss accumulation (no pointer-select on reg arrays)
    float lsum = 0.f;
    {
        const float2* q;
        float4* oq;
        float4* os;

        #define VQ_EMIT(ID, TK, XARR, LANE)                                        \
        {                                                                          \
            q  = s_cb + (ID) * SUBD;                                               \
            oq = (float4*)(out_q  + (size_t)(TK) * 256 + c * SUBD);                \
            os = (float4*)(out_st + (size_t)(TK) * 256 + c * SUBD);                \
            _Pragma("unroll")                                                      \
            for (int i = 0; i < 8; i++){                                           \
                float4 qv, sv;                                                     \
                float* pq = (float*)&qv; float* ps = (float*)&sv;                  \
                _Pragma("unroll")                                                  \
                for (int j = 0; j < 4; j++){                                       \
                    int d = 4*i + j;                                               \
                    float xlo, xhi; unpack2(XARR[d], xlo, xhi);                    \
                    float xv = (LANE) ? xhi : xlo;                                 \
                    float qvv = q[d].x;                                            \
                    pq[j] = qvv;                                                   \
                    ps[j] = __fadd_rn(xv, __fsub_rn(qvv, xv));                     \
                    float e = xv - qvv;                                            \
                    lsum = fmaf(e, e, lsum);                                       \
                }                                                                  \
                oq[i] = qv;                                                        \
                os[i] = sv;                                                        \
            }                                                                      \
            out_ids[(size_t)(TK) * NCB + c] = (float)(ID);                         \
        }

        VQ_EMIT(ia0, t0, xA, 0)
        VQ_EMIT(ia1, t1, xA, 1)
        VQ_EMIT(ib0, t2, xB, 0)
        VQ_EMIT(ib1, t3, xB, 1)
        #undef VQ_EMIT
    }

    atomicAdd(&s_hist[ia0], mask[t0]);
    atomicAdd(&s_hist[ia1], mask[t1]);
    atomicAdd(&s_hist[ib0], mask[t2]);
    atomicAdd(&s_hist[ib1], mask[t3]);

    s_red[tid] = (double)lsum;
    __syncthreads();
    for (int s = TPB / 2; s > 0; s >>= 1){
        if (tid < s) s_red[tid] += s_red[tid + s];
        __syncthreads();
    }
    if (tid == 0) atomicAdd(&g_sqsum, s_red[0]);
    atomicAdd(&g_hist[c * KCODES + tid], s_hist[tid]);
    atomicAdd(&g_hist[c * KCODES + tid + TPB], s_hist[tid + TPB]);
}

__global__ void vq_finalize(const float* __restrict__ mask,
                            float* __restrict__ out_scalars,
                            int ntok)
{
    __shared__ double dred[512];
    __shared__ float  fred[512];
    __shared__ float  pp[NCB];
    int tid = threadIdx.x;

    double s = 0.0;
    for (int i = tid; i < ntok; i += 512) s += (double)mask[i];
    dred[tid] = s; __syncthreads();
    for (int st = 256; st > 0; st >>= 1){
        if (tid < st) dred[tid] += dred[tid + st];
        __syncthreads();
    }
    float denom = fmaxf((float)dred[0], 1.0f);

    for (int c = 0; c < NCB; c++){
        float p = __fdiv_rn(g_hist[c * KCODES + tid], denom);
        float t = __fmul_rn(p, logf(__fadd_rn(p, 1e-8f)));
        fred[tid] = t; __syncthreads();
        for (int st = 256; st > 0; st >>= 1){
            if (tid < st) fred[tid] += fred[tid + st];
            __syncthreads();
        }
        if (tid == 0) pp[c] = expf(-fred[0]);
        __syncthreads();
    }
    if (tid == 0){
        float ppl = (((((((pp[0] + pp[1]) + pp[2]) + pp[3]) + pp[4]) + pp[5]) + pp[6]) + pp[7]) / 8.f;
        double cnt = (double)ntok * 256.0;
        double mse = g_sqsum / cnt;
        out_scalars[0] = (float)(mse * 0.25);  // commitment_loss
        out_scalars[1] = (float)mse;           // codebook_loss
        out_scalars[2] = ppl;                  // perplexity
    }
}

extern "C" void kernel_launch(void* const* d_in, const int* in_sizes, int n_in,
                              void* d_out, int out_size)
{
    const float* latents   = (const float*)d_in[0];
    const float* mask      = (const float*)d_in[1];
    const float* codebooks = (const float*)d_in[2];
    float* out = (float*)d_out;

    const int ntok = in_sizes[1];           // B*N = 65536
    const size_t ids_n = (size_t)ntok * NCB;
    const size_t qn    = (size_t)ntok * 256;

    float* out_ids = out;
    float* out_q   = out + ids_n;
    float* out_st  = out_q + qn;
    float* out_sc  = out_st + qn;

    cudaFuncSetAttribute(vq_main, cudaFuncAttributeMaxDynamicSharedMemorySize, SM_TOTAL);

    vq_zero<<<8, 512>>>();
    vq_pad<<<1, 32>>>();   // launch-index padding so ncu -s 5 captures vq_main
    vq_pad<<<1, 32>>>();
    dim3 grid(ntok / (4 * TPB), NCB);
    vq_main<<<grid, TPB, SM_TOTAL>>>(latents, mask, codebooks, out_ids, out_q, out_st);
    vq_finalize<<<1, 512>>>(mask, out_sc, ntok);
}

// round 4
// speedup vs baseline: 1.4116x; 1.2028x over previous
#include <cuda_runtime.h>
#include <cstdint>

typedef unsigned long long ull;

// ---------- packed f32x2 helpers (each half is an exact IEEE fp32 op) ----------
__device__ __forceinline__ ull pack2(float lo, float hi){
    ull r; asm("mov.b64 %0, {%1,%2};" : "=l"(r) : "f"(lo), "f"(hi)); return r;
}
__device__ __forceinline__ void unpack2(ull v, float& lo, float& hi){
    asm("mov.b64 {%0,%1}, %2;" : "=f"(lo), "=f"(hi) : "l"(v));
}
__device__ __forceinline__ ull fma2(ull a, ull b, ull c){
    ull d; asm("fma.rn.f32x2 %0, %1, %2, %3;" : "=l"(d) : "l"(a), "l"(b), "l"(c)); return d;
}

// ---------- problem constants ----------
constexpr int KCODES = 512;
constexpr int SUBD   = 32;
constexpr int NCB    = 8;
constexpr int TPB    = 256;     // 4 tokens per thread -> 1024 tokens per block

// ---------- scratch (no allocation allowed) ----------
__device__ double g_sqsum;
__device__ float  g_hist[NCB * KCODES];

__global__ void vq_zero(){
    int i = blockIdx.x * blockDim.x + threadIdx.x;
    if (i < NCB * KCODES) g_hist[i] = 0.f;
    if (i == 0) g_sqsum = 0.0;
}

// pad kernels: shift launch indices so ncu (-s 5 -c 1) lands on vq_main
__global__ void vq_pad(){}

// shared memory layout (plain, non-duplicated codebook: 64KB)
constexpr int SM_CB   = KCODES * SUBD * (int)sizeof(float);  // 65536
constexpr int SM_C2   = KCODES * (int)sizeof(float);         // 2048
constexpr int SM_HIST = KCODES * (int)sizeof(float);         // 2048
constexpr int SM_RED  = TPB * (int)sizeof(double);           // 2048
constexpr int SM_TOTAL = SM_CB + SM_C2 + SM_HIST + SM_RED;

__global__ __launch_bounds__(TPB, 1)
void vq_main(const float* __restrict__ latents,
             const float* __restrict__ mask,
             const float* __restrict__ codebooks,
             float* __restrict__ out_ids,
             float* __restrict__ out_q,
             float* __restrict__ out_st)
{
    extern __shared__ char smem[];
    float*  s_cb   = (float*) (smem);
    float*  s_c2   = (float*) (smem + SM_CB);
    float*  s_hist = (float*) (smem + SM_CB + SM_C2);
    double* s_red  = (double*)(smem + SM_CB + SM_C2 + SM_HIST);

    const int c   = blockIdx.y;
    const int tid = threadIdx.x;

    // copy codebook c (plain) into smem, vectorized
    {
        const float4* src = (const float4*)(codebooks + (size_t)c * KCODES * SUBD);
        float4* dst = (float4*)s_cb;
        #pragma unroll
        for (int i = tid; i < KCODES * SUBD / 4; i += TPB) dst[i] = src[i];
    }
    s_hist[tid] = 0.f;
    s_hist[tid + TPB] = 0.f;
    __syncthreads();

    // c2[k] = sum_d round(e*e), sequential ascending (replicates (codebooks**2).sum(-1))
    #pragma unroll
    for (int k = tid; k < KCODES; k += TPB){
        float acc = 0.f;
        const float* row = s_cb + k * SUBD;
        #pragma unroll
        for (int d = 0; d < SUBD; d++){
            float e = row[d];
            acc = __fadd_rn(acc, __fmul_rn(e, e));
        }
        s_c2[k] = acc;
    }
    __syncthreads();

    // 4 tokens per thread
    const int t0 = blockIdx.x * (4 * TPB) + tid;
    const int t1 = t0 + TPB;
    const int t2 = t0 + 2 * TPB;
    const int t3 = t0 + 3 * TPB;

    // x packed by DIMS: xT[m] = {x[2m], x[2m+1]}; x2 sequential ascending
    ull xT0[16], xT1[16], xT2[16], xT3[16];
    float x20, x21, x22, x23;

    #define VQ_LOAD(TK, XARR, X2)                                              \
    {                                                                          \
        const float4* p = (const float4*)(latents + (size_t)(TK) * 256 + c * SUBD); \
        float acc = 0.f;                                                       \
        _Pragma("unroll")                                                      \
        for (int i = 0; i < 8; i++){                                           \
            float4 f = p[i];                                                   \
            XARR[2*i]   = pack2(f.x, f.y);                                     \
            XARR[2*i+1] = pack2(f.z, f.w);                                     \
            acc = __fadd_rn(acc, __fmul_rn(f.x, f.x));                         \
            acc = __fadd_rn(acc, __fmul_rn(f.y, f.y));                         \
            acc = __fadd_rn(acc, __fmul_rn(f.z, f.z));                         \
            acc = __fadd_rn(acc, __fmul_rn(f.w, f.w));                         \
        }                                                                      \
        X2 = acc;                                                              \
    }
    VQ_LOAD(t0, xT0, x20)
    VQ_LOAD(t1, xT1, x21)
    VQ_LOAD(t2, xT2, x22)
    VQ_LOAD(t3, xT3, x23)
    #undef VQ_LOAD

    float b0 = 3.4e38f, b1 = 3.4e38f, b2 = 3.4e38f, b3 = 3.4e38f;
    int i0 = 0, i1 = 0, i2 = 0, i3 = 0;

    const float2* c2p = (const float2*)s_c2;

    // two codes per iteration; 8 independent fma2 chains; per code only 8 LDS.128
    #pragma unroll 2
    for (int k = 0; k < KCODES; k += 2){
        const ulonglong2* e = (const ulonglong2*)(s_cb + k * SUBD);
        ull s00 = 0, s10 = 0, s20 = 0, s30 = 0;   // code k,   tokens 0..3
        ull s01 = 0, s11 = 0, s21 = 0, s31 = 0;   // code k+1, tokens 0..3
        #pragma unroll
        for (int j = 0; j < 8; j++){
            ulonglong2 ea = e[j];       // code k:   dims 4j..4j+3
            ulonglong2 eb = e[j + 8];   // code k+1: dims 4j..4j+3
            s00 = fma2(xT0[2*j],   ea.x, s00);
            s10 = fma2(xT1[2*j],   ea.x, s10);
            s20 = fma2(xT2[2*j],   ea.x, s20);
            s30 = fma2(xT3[2*j],   ea.x, s30);
            s01 = fma2(xT0[2*j],   eb.x, s01);
            s11 = fma2(xT1[2*j],   eb.x, s11);
            s21 = fma2(xT2[2*j],   eb.x, s21);
            s31 = fma2(xT3[2*j],   eb.x, s31);
            s00 = fma2(xT0[2*j+1], ea.y, s00);
            s10 = fma2(xT1[2*j+1], ea.y, s10);
            s20 = fma2(xT2[2*j+1], ea.y, s20);
            s30 = fma2(xT3[2*j+1], ea.y, s30);
            s01 = fma2(xT0[2*j+1], eb.y, s01);
            s11 = fma2(xT1[2*j+1], eb.y, s11);
            s21 = fma2(xT2[2*j+1], eb.y, s21);
            s31 = fma2(xT3[2*j+1], eb.y, s31);
        }
        float2 c2v = c2p[k >> 1];
        float lo, hi, dot, term, dist;
        // term = round(x2 + c2); dist = round(term - 2*dot) — identical to reference formula
        #define VQ_FIN(S, X2, C2, BEST, IDX, KK)                  \
        {                                                         \
            unpack2(S, lo, hi);                                   \
            dot  = __fadd_rn(lo, hi);                             \
            term = __fadd_rn(X2, C2);                             \
            dist = __fmaf_rn(dot, -2.f, term);                    \
            if (dist < BEST){ BEST = dist; IDX = (KK); }          \
        }
        VQ_FIN(s00, x20, c2v.x, b0, i0, k)
        VQ_FIN(s10, x21, c2v.x, b1, i1, k)
        VQ_FIN(s20, x22, c2v.x, b2, i2, k)
        VQ_FIN(s30, x23, c2v.x, b3, i3, k)
        VQ_FIN(s01, x20, c2v.y, b0, i0, k + 1)
        VQ_FIN(s11, x21, c2v.y, b1, i1, k + 1)
        VQ_FIN(s21, x22, c2v.y, b2, i2, k + 1)
        VQ_FIN(s31, x23, c2v.y, b3, i3, k + 1)
        #undef VQ_FIN
    }

    // epilogue: quant, st_quantized, loss accumulation
    float lsum = 0.f;
    {
        #define VQ_EMIT(ID, TK, XARR)                                              \
        {                                                                          \
            const float4* q = (const float4*)(s_cb + (ID) * SUBD);                 \
            float4* oq = (float4*)(out_q  + (size_t)(TK) * 256 + c * SUBD);        \
            float4* os = (float4*)(out_st + (size_t)(TK) * 256 + c * SUBD);        \
            _Pragma("unroll")                                                      \
            for (int i = 0; i < 8; i++){                                           \
                float4 qv = q[i];                                                  \
                float4 sv;                                                         \
                float x0v, x1v, x2v, x3v;                                          \
                unpack2(XARR[2*i],   x0v, x1v);                                    \
                unpack2(XARR[2*i+1], x2v, x3v);                                    \
                sv.x = __fadd_rn(x0v, __fsub_rn(qv.x, x0v));                       \
                sv.y = __fadd_rn(x1v, __fsub_rn(qv.y, x1v));                       \
                sv.z = __fadd_rn(x2v, __fsub_rn(qv.z, x2v));                       \
                sv.w = __fadd_rn(x3v, __fsub_rn(qv.w, x3v));                       \
                float e0 = x0v - qv.x, e1 = x1v - qv.y;                            \
                float e2 = x2v - qv.z, e3 = x3v - qv.w;                            \
                lsum = fmaf(e0, e0, lsum);                                         \
                lsum = fmaf(e1, e1, lsum);                                         \
                lsum = fmaf(e2, e2, lsum);                                         \
                lsum = fmaf(e3, e3, lsum);                                         \
                oq[i] = qv;                                                        \
                os[i] = sv;                                                        \
            }                                                                      \
            out_ids[(size_t)(TK) * NCB + c] = (float)(ID);                         \
        }
        VQ_EMIT(i0, t0, xT0)
        VQ_EMIT(i1, t1, xT1)
        VQ_EMIT(i2, t2, xT2)
        VQ_EMIT(i3, t3, xT3)
        #undef VQ_EMIT
    }

    atomicAdd(&s_hist[i0], mask[t0]);
    atomicAdd(&s_hist[i1], mask[t1]);
    atomicAdd(&s_hist[i2], mask[t2]);
    atomicAdd(&s_hist[i3], mask[t3]);

    s_red[tid] = (double)lsum;
    __syncthreads();
    for (int s = TPB / 2; s > 0; s >>= 1){
        if (tid < s) s_red[tid] += s_red[tid + s];
        __syncthreads();
    }
    if (tid == 0) atomicAdd(&g_sqsum, s_red[0]);
    atomicAdd(&g_hist[c * KCODES + tid], s_hist[tid]);
    atomicAdd(&g_hist[c * KCODES + tid + TPB], s_hist[tid + TPB]);
}

__global__ void vq_finalize(const float* __restrict__ mask,
                            float* __restrict__ out_scalars,
                            int ntok)
{
    __shared__ double dred[512];
    __shared__ float  fred[512];
    __shared__ float  pp[NCB];
    int tid = threadIdx.x;

    double s = 0.0;
    for (int i = tid; i < ntok; i += 512) s += (double)mask[i];
    dred[tid] = s; __syncthreads();
    for (int st = 256; st > 0; st >>= 1){
        if (tid < st) dred[tid] += dred[tid + st];
        __syncthreads();
    }
    float denom = fmaxf((float)dred[0], 1.0f);

    for (int c = 0; c < NCB; c++){
        float p = __fdiv_rn(g_hist[c * KCODES + tid], denom);
        float t = __fmul_rn(p, logf(__fadd_rn(p, 1e-8f)));
        fred[tid] = t; __syncthreads();
        for (int st = 256; st > 0; st >>= 1){
            if (tid < st) fred[tid] += fred[tid + st];
            __syncthreads();
        }
        if (tid == 0) pp[c] = expf(-fred[0]);
        __syncthreads();
    }
    if (tid == 0){
        float ppl = (((((((pp[0] + pp[1]) + pp[2]) + pp[3]) + pp[4]) + pp[5]) + pp[6]) + pp[7]) / 8.f;
        double cnt = (double)ntok * 256.0;
        double mse = g_sqsum / cnt;
        out_scalars[0] = (float)(mse * 0.25);  // commitment_loss
        out_scalars[1] = (float)mse;           // codebook_loss
        out_scalars[2] = ppl;                  // perplexity
    }
}

extern "C" void kernel_launch(void* const* d_in, const int* in_sizes, int n_in,
                              void* d_out, int out_size)
{
    const float* latents   = (const float*)d_in[0];
    const float* mask      = (const float*)d_in[1];
    const float* codebooks = (const float*)d_in[2];
    float* out = (float*)d_out;

    const int ntok = in_sizes[1];           // B*N = 65536
    const size_t ids_n = (size_t)ntok * NCB;
    const size_t qn    = (size_t)ntok * 256;

    float* out_ids = out;
    float* out_q   = out + ids_n;
    float* out_st  = out_q + qn;
    float* out_sc  = out_st + qn;

    cudaFuncSetAttribute(vq_main, cudaFuncAttributeMaxDynamicSharedMemorySize, SM_TOTAL);

    vq_zero<<<8, 512>>>();
    vq_pad<<<1, 32>>>();   // launch-index padding so ncu -s 5 captures vq_main
    vq_pad<<<1, 32>>>();
    dim3 grid(ntok / (4 * TPB), NCB);
    vq_main<<<grid, TPB, SM_TOTAL>>>(latents, mask, codebooks, out_ids, out_q, out_st);
    vq_finalize<<<1, 512>>>(mask, out_sc, ntok);
}

// round 5
// speedup vs baseline: 1.5789x; 1.1185x over previous
#include <cuda_runtime.h>
#include <cstdint>

typedef unsigned long long ull;

// ---------- packed f32x2 helpers (each half is an exact IEEE fp32 op) ----------
__device__ __forceinline__ ull pack2(float lo, float hi){
    ull r; asm("mov.b64 %0, {%1,%2};" : "=l"(r) : "f"(lo), "f"(hi)); return r;
}
__device__ __forceinline__ void unpack2(ull v, float& lo, float& hi){
    asm("mov.b64 {%0,%1}, %2;" : "=f"(lo), "=f"(hi) : "l"(v));
}
__device__ __forceinline__ ull fma2(ull a, ull b, ull c){
    ull d; asm("fma.rn.f32x2 %0, %1, %2, %3;" : "=l"(d) : "l"(a), "l"(b), "l"(c)); return d;
}

// ---------- problem constants ----------
constexpr int KCODES = 512;
constexpr int SUBD   = 32;
constexpr int NCB    = 8;
constexpr int TPB    = 256;     // 2 tokens per thread -> 512 tokens per block

// ---------- scratch (no allocation allowed) ----------
__device__ double g_sqsum;
__device__ float  g_hist[NCB * KCODES];

__global__ void vq_zero(){
    int i = blockIdx.x * blockDim.x + threadIdx.x;
    if (i < NCB * KCODES) g_hist[i] = 0.f;
    if (i == 0) g_sqsum = 0.0;
}

// pad kernels: shift launch indices so ncu (-s 5 -c 1) lands on vq_main
__global__ void vq_pad(){}

// shared memory layout (plain codebook: 64KB) — 2 CTAs/SM => 143KB total, fits
constexpr int SM_CB   = KCODES * SUBD * (int)sizeof(float);  // 65536
constexpr int SM_C2   = KCODES * (int)sizeof(float);         // 2048
constexpr int SM_HIST = KCODES * (int)sizeof(float);         // 2048
constexpr int SM_RED  = TPB * (int)sizeof(double);           // 2048
constexpr int SM_TOTAL = SM_CB + SM_C2 + SM_HIST + SM_RED;

__global__ __launch_bounds__(TPB, 2)   // force <=128 regs -> 2 CTAs/SM (16 warps)
void vq_main(const float* __restrict__ latents,
             const float* __restrict__ mask,
             const float* __restrict__ codebooks,
             float* __restrict__ out_ids,
             float* __restrict__ out_q,
             float* __restrict__ out_st)
{
    extern __shared__ char smem[];
    float*  s_cb   = (float*) (smem);
    float*  s_c2   = (float*) (smem + SM_CB);
    float*  s_hist = (float*) (smem + SM_CB + SM_C2);
    double* s_red  = (double*)(smem + SM_CB + SM_C2 + SM_HIST);

    const int c   = blockIdx.y;
    const int tid = threadIdx.x;

    // copy codebook c (plain) into smem, vectorized
    {
        const float4* src = (const float4*)(codebooks + (size_t)c * KCODES * SUBD);
        float4* dst = (float4*)s_cb;
        #pragma unroll
        for (int i = tid; i < KCODES * SUBD / 4; i += TPB) dst[i] = src[i];
    }
    s_hist[tid] = 0.f;
    s_hist[tid + TPB] = 0.f;
    __syncthreads();

    // c2[k] = sum_d round(e*e), sequential ascending (replicates (codebooks**2).sum(-1))
    #pragma unroll
    for (int k = tid; k < KCODES; k += TPB){
        float acc = 0.f;
        const float* row = s_cb + k * SUBD;
        #pragma unroll
        for (int d = 0; d < SUBD; d++){
            float e = row[d];
            acc = __fadd_rn(acc, __fmul_rn(e, e));
        }
        s_c2[k] = acc;
    }
    __syncthreads();

    // 2 tokens per thread
    const int t0 = blockIdx.x * (2 * TPB) + tid;
    const int t1 = t0 + TPB;

    // x packed by DIMS: xT[m] = {x[2m], x[2m+1]}; x2 sequential ascending
    ull xT0[16], xT1[16];
    float x20, x21;

    #define VQ_LOAD(TK, XARR, X2)                                              \
    {                                                                          \
        const float4* p = (const float4*)(latents + (size_t)(TK) * 256 + c * SUBD); \
        float acc = 0.f;                                                       \
        _Pragma("unroll")                                                      \
        for (int i = 0; i < 8; i++){                                           \
            float4 f = p[i];                                                   \
            XARR[2*i]   = pack2(f.x, f.y);                                     \
            XARR[2*i+1] = pack2(f.z, f.w);                                     \
            acc = __fadd_rn(acc, __fmul_rn(f.x, f.x));                         \
            acc = __fadd_rn(acc, __fmul_rn(f.y, f.y));                         \
            acc = __fadd_rn(acc, __fmul_rn(f.z, f.z));                         \
            acc = __fadd_rn(acc, __fmul_rn(f.w, f.w));                         \
        }                                                                      \
        X2 = acc;                                                              \
    }
    VQ_LOAD(t0, xT0, x20)
    VQ_LOAD(t1, xT1, x21)
    #undef VQ_LOAD

    float b0 = 3.4e38f, b1 = 3.4e38f;
    int i0 = 0, i1 = 0;

    const float2* c2p = (const float2*)s_c2;

    // two codes per iteration; 4 independent fma2 chains; 16 LDS.128 per k-pair
    #pragma unroll 1
    for (int k = 0; k < KCODES; k += 2){
        const ulonglong2* e = (const ulonglong2*)(s_cb + k * SUBD);
        ull s00 = 0, s10 = 0;   // code k,   tokens 0,1
        ull s01 = 0, s11 = 0;   // code k+1, tokens 0,1
        #pragma unroll
        for (int j = 0; j < 8; j++){
            ulonglong2 ea = e[j];       // code k:   dims 4j..4j+3
            ulonglong2 eb = e[j + 8];   // code k+1: dims 4j..4j+3
            s00 = fma2(xT0[2*j],   ea.x, s00);
            s10 = fma2(xT1[2*j],   ea.x, s10);
            s01 = fma2(xT0[2*j],   eb.x, s01);
            s11 = fma2(xT1[2*j],   eb.x, s11);
            s00 = fma2(xT0[2*j+1], ea.y, s00);
            s10 = fma2(xT1[2*j+1], ea.y, s10);
            s01 = fma2(xT0[2*j+1], eb.y, s01);
            s11 = fma2(xT1[2*j+1], eb.y, s11);
        }
        float2 c2v = c2p[k >> 1];
        float lo, hi, dot, term, dist;
        // term = round(x2 + c2); dist = round(term - 2*dot) — identical to reference formula
        #define VQ_FIN(S, X2, C2, BEST, IDX, KK)                  \
        {                                                         \
            unpack2(S, lo, hi);                                   \
            dot  = __fadd_rn(lo, hi);                             \
            term = __fadd_rn(X2, C2);                             \
            dist = __fmaf_rn(dot, -2.f, term);                    \
            if (dist < BEST){ BEST = dist; IDX = (KK); }          \
        }
        VQ_FIN(s00, x20, c2v.x, b0, i0, k)
        VQ_FIN(s10, x21, c2v.x, b1, i1, k)
        VQ_FIN(s01, x20, c2v.y, b0, i0, k + 1)
        VQ_FIN(s11, x21, c2v.y, b1, i1, k + 1)
        #undef VQ_FIN
    }

    // epilogue: quant, st_quantized, loss accumulation
    float lsum = 0.f;
    {
        #define VQ_EMIT(ID, TK, XARR)                                              \
        {                                                                          \
            const float4* q = (const float4*)(s_cb + (ID) * SUBD);                 \
            float4* oq = (float4*)(out_q  + (size_t)(TK) * 256 + c * SUBD);        \
            float4* os = (float4*)(out_st + (size_t)(TK) * 256 + c * SUBD);        \
            _Pragma("unroll")                                                      \
            for (int i = 0; i < 8; i++){                                           \
                float4 qv = q[i];                                                  \
                float4 sv;                                                         \
                float x0v, x1v, x2v, x3v;                                          \
                unpack2(XARR[2*i],   x0v, x1v);                                    \
                unpack2(XARR[2*i+1], x2v, x3v);                                    \
                sv.x = __fadd_rn(x0v, __fsub_rn(qv.x, x0v));                       \
                sv.y = __fadd_rn(x1v, __fsub_rn(qv.y, x1v));                       \
                sv.z = __fadd_rn(x2v, __fsub_rn(qv.z, x2v));                       \
                sv.w = __fadd_rn(x3v, __fsub_rn(qv.w, x3v));                       \
                float e0 = x0v - qv.x, e1 = x1v - qv.y;                            \
                float e2 = x2v - qv.z, e3 = x3v - qv.w;                            \
                lsum = fmaf(e0, e0, lsum);                                         \
                lsum = fmaf(e1, e1, lsum);                                         \
                lsum = fmaf(e2, e2, lsum);                                         \
                lsum = fmaf(e3, e3, lsum);                                         \
                oq[i] = qv;                                                        \
                os[i] = sv;                                                        \
            }                                                                      \
            out_ids[(size_t)(TK) * NCB + c] = (float)(ID);                         \
        }
        VQ_EMIT(i0, t0, xT0)
        VQ_EMIT(i1, t1, xT1)
        #undef VQ_EMIT
    }

    atomicAdd(&s_hist[i0], mask[t0]);
    atomicAdd(&s_hist[i1], mask[t1]);

    s_red[tid] = (double)lsum;
    __syncthreads();
    for (int s = TPB / 2; s > 0; s >>= 1){
        if (tid < s) s_red[tid] += s_red[tid + s];
        __syncthreads();
    }
    if (tid == 0) atomicAdd(&g_sqsum, s_red[0]);
    atomicAdd(&g_hist[c * KCODES + tid], s_hist[tid]);
    atomicAdd(&g_hist[c * KCODES + tid + TPB], s_hist[tid + TPB]);
}

__global__ void vq_finalize(const float* __restrict__ mask,
                            float* __restrict__ out_scalars,
                            int ntok)
{
    __shared__ double dred[512];
    __shared__ float  fred[512];
    __shared__ float  pp[NCB];
    int tid = threadIdx.x;

    double s = 0.0;
    for (int i = tid; i < ntok; i += 512) s += (double)mask[i];
    dred[tid] = s; __syncthreads();
    for (int st = 256; st > 0; st >>= 1){
        if (tid < st) dred[tid] += dred[tid + st];
        __syncthreads();
    }
    float denom = fmaxf((float)dred[0], 1.0f);

    for (int c = 0; c < NCB; c++){
        float p = __fdiv_rn(g_hist[c * KCODES + tid], denom);
        float t = __fmul_rn(p, logf(__fadd_rn(p, 1e-8f)));
        fred[tid] = t; __syncthreads();
        for (int st = 256; st > 0; st >>= 1){
            if (tid < st) fred[tid] += fred[tid + st];
            __syncthreads();
        }
        if (tid == 0) pp[c] = expf(-fred[0]);
        __syncthreads();
    }
    if (tid == 0){
        float ppl = (((((((pp[0] + pp[1]) + pp[2]) + pp[3]) + pp[4]) + pp[5]) + pp[6]) + pp[7]) / 8.f;
        double cnt = (double)ntok * 256.0;
        double mse = g_sqsum / cnt;
        out_scalars[0] = (float)(mse * 0.25);  // commitment_loss
        out_scalars[1] = (float)mse;           // codebook_loss
        out_scalars[2] = ppl;                  // perplexity
    }
}

extern "C" void kernel_launch(void* const* d_in, const int* in_sizes, int n_in,
                              void* d_out, int out_size)
{
    const float* latents   = (const float*)d_in[0];
    const float* mask      = (const float*)d_in[1];
    const float* codebooks = (const float*)d_in[2];
    float* out = (float*)d_out;

    const int ntok = in_sizes[1];           // B*N = 65536
    const size_t ids_n = (size_t)ntok * NCB;
    const size_t qn    = (size_t)ntok * 256;

    float* out_ids = out;
    float* out_q   = out + ids_n;
    float* out_st  = out_q + qn;
    float* out_sc  = out_st + qn;

    cudaFuncSetAttribute(vq_main, cudaFuncAttributeMaxDynamicSharedMemorySize, SM_TOTAL);

    vq_zero<<<8, 512>>>();
    vq_pad<<<1, 32>>>();   // launch-index padding so ncu -s 5 captures vq_main
    vq_pad<<<1, 32>>>();
    dim3 grid(ntok / (2 * TPB), NCB);
    vq_main<<<grid, TPB, SM_TOTAL>>>(latents, mask, codebooks, out_ids, out_q, out_st);
    vq_finalize<<<1, 512>>>(mask, out_sc, ntok);
}